// round 5
// baseline (speedup 1.0000x reference)
#include <cuda_runtime.h>
#include <cuda_fp16.h>
#include <cstdint>

#define DD    64
#define HATTN 256
#define NMAX  2048

// ---------------- device-global scratch (no allocs allowed) ----------------
__device__ float  g_Wqa[DD * HATTN];
__device__ float  g_Wka[DD * HATTN];
__device__ float  g_W12[DD * HATTN];      // (pW2@aW1)[h][c]
__device__ float  g_bqa[HATTN];
__device__ float  g_qa [NMAX * HATTN];    // fp32
__device__ __half g_ax [NMAX * 128];      // per row: [d_j(64) | x_j(64)], d = pos@pW1 (no bias)
// fp16 B-fragment images: uint2 = {half2(k0,k0+1), half2(k0+8,k0+9)} at col n0
__device__ uint2  g_W12f[8192];           // B1 = [W12; -Wka] : [kk=8][nt=32][lane=32]
__device__ uint2  g_aW2f[4096];           // aW2             : [kk=16][nt=8][lane=32]
__device__ uint2  g_Wvvf[2048];           // [pW2; Wv]       : [kk=8][nt=8][lane=32]

__device__ __forceinline__ unsigned fp2h2(float a, float b) {
    __half2 h = __floats2half2_rn(a, b);
    return *reinterpret_cast<unsigned*>(&h);
}
__device__ __forceinline__ void mma16(float* c, const unsigned* a, uint2 b) {
    asm volatile("mma.sync.aligned.m16n8k16.row.col.f32.f16.f16.f32 "
                 "{%0,%1,%2,%3}, {%4,%5,%6,%7}, {%8,%9}, {%0,%1,%2,%3};"
                 : "+f"(c[0]), "+f"(c[1]), "+f"(c[2]), "+f"(c[3])
                 : "r"(a[0]), "r"(a[1]), "r"(a[2]), "r"(a[3]), "r"(b.x), "r"(b.y));
}

// ---------------------------------------------------------------------------
// prep1: weight folds W12 = pW2@aW1, Wqa = Wq@aW1, Wka = Wk@aW1, bqa.
// ---------------------------------------------------------------------------
__global__ void prep1(const float* __restrict__ Wq, const float* __restrict__ Wk,
                      const float* __restrict__ pW2, const float* __restrict__ aW1,
                      const float* __restrict__ ab1, const float* __restrict__ pb2)
{
    __shared__ float srow[3][DD];
    const int r = blockIdx.x, c = threadIdx.x;
    if (c < 64)       srow[0][c]       = Wq [r * DD + c];
    else if (c < 128) srow[1][c - 64]  = Wk [r * DD + (c - 64)];
    else if (c < 192) srow[2][c - 128] = pW2[r * DD + (c - 128)];
    __syncthreads();
    float wq = 0.f, wk = 0.f, w12 = 0.f;
    #pragma unroll 8
    for (int t = 0; t < DD; ++t) {
        float a = aW1[t * HATTN + c];
        wq  = fmaf(srow[0][t], a, wq);
        wk  = fmaf(srow[1][t], a, wk);
        w12 = fmaf(srow[2][t], a, w12);
    }
    g_Wqa[r * HATTN + c] = wq;
    g_Wka[r * HATTN + c] = wk;
    g_W12[r * HATTN + c] = w12;
    if (r == 0) {
        float b = ab1[c];
        for (int t = 0; t < DD; ++t) b = fmaf(pb2[t], aW1[t * HATTN + c], b);
        g_bqa[c] = b;
    }
}

// ---------------------------------------------------------------------------
// prepF: pack [W12;-Wka] / aW2 / [pW2;Wv] into fp16 B-fragment images.
// grid = 56 x 256 (14336 fragment entries).
// ---------------------------------------------------------------------------
__global__ void prepF(const float* __restrict__ aW2, const float* __restrict__ pW2,
                      const float* __restrict__ Wv)
{
    const int e = blockIdx.x * 256 + threadIdx.x;
    const int lane = e & 31, gg = lane >> 2, tg = lane & 3;
    if (e < 8192) {                                      // B1 = [W12; -Wka], K=128, N=256
        const int kk = e >> 10, nt = (e >> 5) & 31;
        const int k0 = 16 * kk + 2 * tg, n0 = 8 * nt + gg;
        auto val = [&](int k) {
            return (k < 64) ? g_W12[k * HATTN + n0] : -g_Wka[(k - 64) * HATTN + n0];
        };
        uint2 v;
        v.x = fp2h2(val(k0),     val(k0 + 1));
        v.y = fp2h2(val(k0 + 8), val(k0 + 9));
        g_W12f[e] = v;
    } else if (e < 12288) {                              // aW2, K=256, N=64
        const int l = e - 8192;
        const int kk = l >> 8, nt = (l >> 5) & 7;
        const int k0 = 16 * kk + 2 * tg, n0 = 8 * nt + gg;
        uint2 v;
        v.x = fp2h2(aW2[(k0    ) * DD + n0], aW2[(k0 + 1) * DD + n0]);
        v.y = fp2h2(aW2[(k0 + 8) * DD + n0], aW2[(k0 + 9) * DD + n0]);
        g_aW2f[l] = v;
    } else if (e < 14336) {                              // [pW2; Wv], K=128, N=64
        const int l = e - 12288;
        const int kk = l >> 8, nt = (l >> 5) & 7;
        const int k0 = 16 * kk + 2 * tg, n0 = 8 * nt + gg;
        auto val = [&](int k) {
            return (k < 64) ? pW2[k * DD + n0] : Wv[(k - 64) * DD + n0];
        };
        uint2 v;
        v.x = fp2h2(val(k0),     val(k0 + 1));
        v.y = fp2h2(val(k0 + 8), val(k0 + 9));
        g_Wvvf[l] = v;
    }
}

// ---------------------------------------------------------------------------
// prep2: qa (fp32) + packed [d|x] row image (fp16). grid N x 256.
// ---------------------------------------------------------------------------
__global__ void prep2(const float* __restrict__ x, const float* __restrict__ pos,
                      const float* __restrict__ pW1, int N)
{
    __shared__ float sx[DD];
    const int n = blockIdx.x, c = threadIdx.x;
    if (c < DD) sx[c] = x[n * DD + c];
    __syncthreads();
    float aq = g_bqa[c];
    #pragma unroll 8
    for (int t = 0; t < DD; ++t) aq = fmaf(sx[t], g_Wqa[t * HATTN + c], aq);
    g_qa[n * HATTN + c] = aq;
    if (c < DD) {
        g_ax[n * 128 + c] = __float2half(fmaf(pos[2 * n], pW1[c],
                                              pos[2 * n + 1] * pW1[DD + c]));
        g_ax[n * 128 + 64 + c] = __float2half(sx[c]);
    }
}

// ---------------------------------------------------------------------------
// main: one CTA per query i; 8 warps x 32 rows = 256-row j-tiles, warp-local.
// All j-data enters through GEMM K-extension; gmem loads front-batched.
// ---------------------------------------------------------------------------
#define OFF_W12F 0
#define OFF_AW2F 65536
#define OFF_WVVF 98304
#define OFF_QA   114688
#define OFF_CI   115712
#define OFF_REDS 115968
#define OFF_REDA 118016
#define SMEM_SZ  120064

__global__ void __launch_bounds__(256, 1)
pt_main(const float* __restrict__ pos, const float* __restrict__ pW1,
        const float* __restrict__ pb1, const float* __restrict__ pb2,
        float* __restrict__ out, int N)
{
    extern __shared__ char smem[];
    uint2* sW12f = (uint2*)(smem + OFF_W12F);
    uint2* sAW2f = (uint2*)(smem + OFF_AW2F);
    uint2* sWVVf = (uint2*)(smem + OFF_WVVF);
    float* sQa   = (float*)(smem + OFF_QA);
    float* sCi   = (float*)(smem + OFF_CI);
    float* sRedS = (float*)(smem + OFF_REDS);
    float* sRedA = (float*)(smem + OFF_REDA);

    const int tid  = threadIdx.x;
    const int i    = blockIdx.x;
    const int w    = tid >> 5, lane = tid & 31;
    const int g    = lane >> 2, tig = lane & 3;

    {   // stage fragment images
        uint4* d1 = (uint4*)sW12f;  const uint4* s1 = (const uint4*)g_W12f;
        uint4* d2 = (uint4*)sAW2f;  const uint4* s2 = (const uint4*)g_aW2f;
        uint4* d3 = (uint4*)sWVVf;  const uint4* s3 = (const uint4*)g_Wvvf;
        for (int k = tid; k < 4096; k += 256) d1[k] = s1[k];
        for (int k = tid; k < 2048; k += 256) d2[k] = s2[k];
        for (int k = tid; k < 1024; k += 256) d3[k] = s3[k];
    }
    sQa[tid] = g_qa[i * HATTN + tid];
    const float posIx = pos[2 * i], posIy = pos[2 * i + 1];
    if (tid < 64)
        sCi[tid] = fmaf(posIx, pW1[tid], fmaf(posIy, pW1[DD + tid], pb1[tid]));
    sRedS[tid] = 0.f; sRedS[tid + 256] = 0.f;
    sRedA[tid] = 0.f; sRedA[tid + 256] = 0.f;
    __syncthreads();

    const int ntile = N >> 8;
    for (int jt = 0; jt < ntile; ++jt) {
        const int r0 = (jt << 8) + w * 32;

        // ---- front-batched A fragments: Af = [U | x] (K=128) ----
        unsigned Af[2][8][4];
        #pragma unroll
        for (int kk = 0; kk < 4; ++kk) {                 // U = relu(ci - d_j)
            const float c0 = sCi[16 * kk + 2 * tig];
            const float c1 = sCi[16 * kk + 2 * tig + 1];
            const float c2 = sCi[16 * kk + 2 * tig + 8];
            const float c3 = sCi[16 * kk + 2 * tig + 9];
            #pragma unroll
            for (int mt = 0; mt < 2; ++mt) {
                const int rlo = r0 + mt * 16 + g, rhi = rlo + 8;
                float2 dl0 = __half22float2(*(const __half2*)&g_ax[rlo * 128 + 16 * kk + 2 * tig]);
                float2 dl1 = __half22float2(*(const __half2*)&g_ax[rlo * 128 + 16 * kk + 2 * tig + 8]);
                float2 dh0 = __half22float2(*(const __half2*)&g_ax[rhi * 128 + 16 * kk + 2 * tig]);
                float2 dh1 = __half22float2(*(const __half2*)&g_ax[rhi * 128 + 16 * kk + 2 * tig + 8]);
                Af[mt][kk][0] = fp2h2(fmaxf(c0 - dl0.x, 0.f), fmaxf(c1 - dl0.y, 0.f));
                Af[mt][kk][1] = fp2h2(fmaxf(c0 - dh0.x, 0.f), fmaxf(c1 - dh0.y, 0.f));
                Af[mt][kk][2] = fp2h2(fmaxf(c2 - dl1.x, 0.f), fmaxf(c3 - dl1.y, 0.f));
                Af[mt][kk][3] = fp2h2(fmaxf(c2 - dh1.x, 0.f), fmaxf(c3 - dh1.y, 0.f));
            }
        }
        #pragma unroll
        for (int kk = 0; kk < 4; ++kk) {                 // x passthrough
            #pragma unroll
            for (int mt = 0; mt < 2; ++mt) {
                const int rlo = r0 + mt * 16 + g, rhi = rlo + 8;
                Af[mt][4 + kk][0] = *(const unsigned*)&g_ax[rlo * 128 + 64 + 16 * kk + 2 * tig];
                Af[mt][4 + kk][1] = *(const unsigned*)&g_ax[rhi * 128 + 64 + 16 * kk + 2 * tig];
                Af[mt][4 + kk][2] = *(const unsigned*)&g_ax[rlo * 128 + 64 + 16 * kk + 8 + 2 * tig];
                Af[mt][4 + kk][3] = *(const unsigned*)&g_ax[rhi * 128 + 64 + 16 * kk + 8 + 2 * tig];
            }
        }

        float sc[2][8][4];
        #pragma unroll
        for (int mt = 0; mt < 2; ++mt)
            #pragma unroll
            for (int a = 0; a < 8; ++a)
                { sc[mt][a][0]=0.f; sc[mt][a][1]=0.f; sc[mt][a][2]=0.f; sc[mt][a][3]=0.f; }

        #pragma unroll 1
        for (int chk = 0; chk < 8; ++chk) {              // 32 attn channels / chunk
            // GEMM1: P = [U|x] @ [W12;-Wka]  (K=128) -> includes -ka
            float pa[2][4][4];
            #pragma unroll
            for (int mt = 0; mt < 2; ++mt)
                #pragma unroll
                for (int a = 0; a < 4; ++a)
                    { pa[mt][a][0]=0.f; pa[mt][a][1]=0.f; pa[mt][a][2]=0.f; pa[mt][a][3]=0.f; }
            #pragma unroll
            for (int kk = 0; kk < 8; ++kk) {
                uint2 b0 = sW12f[((kk * 32) + (chk * 4 + 0)) * 32 + lane];
                uint2 b1 = sW12f[((kk * 32) + (chk * 4 + 1)) * 32 + lane];
                uint2 b2 = sW12f[((kk * 32) + (chk * 4 + 2)) * 32 + lane];
                uint2 b3 = sW12f[((kk * 32) + (chk * 4 + 3)) * 32 + lane];
                #pragma unroll
                for (int mt = 0; mt < 2; ++mt) {
                    mma16(pa[mt][0], Af[mt][kk], b0);
                    mma16(pa[mt][1], Af[mt][kk], b1);
                    mma16(pa[mt][2], Af[mt][kk], b2);
                    mma16(pa[mt][3], Af[mt][kk], b3);
                }
            }
            // epilogue (register-only): + qa, relu, repack as GEMM2 A-frags
            unsigned a2[2][2][4];
            #pragma unroll
            for (int nt = 0; nt < 4; ++nt) {
                float2 qa2 = *(const float2*)&sQa[chk * 32 + nt * 8 + 2 * tig];
                #pragma unroll
                for (int mt = 0; mt < 2; ++mt) {
                    float v00 = fmaxf(pa[mt][nt][0] + qa2.x, 0.f);
                    float v01 = fmaxf(pa[mt][nt][1] + qa2.y, 0.f);
                    float v10 = fmaxf(pa[mt][nt][2] + qa2.x, 0.f);
                    float v11 = fmaxf(pa[mt][nt][3] + qa2.y, 0.f);
                    const int kk2 = nt >> 1, sl = (nt & 1) << 1;
                    a2[mt][kk2][sl]     = fp2h2(v00, v01);
                    a2[mt][kk2][sl + 1] = fp2h2(v10, v11);
                }
            }
            // GEMM2 partial: sim += P' @ aW2  (K=32 this chunk)
            #pragma unroll
            for (int kk2 = 0; kk2 < 2; ++kk2)
                #pragma unroll
                for (int nt2 = 0; nt2 < 8; ++nt2) {
                    uint2 b = sAW2f[(((chk * 2 + kk2) * 8) + nt2) * 32 + lane];
                    mma16(sc[0][nt2], a2[0][kk2], b);
                    mma16(sc[1][nt2], a2[1][kk2], b);
                }
        }

        // GEMM3: vv' = [U|x] @ [pW2;Wv]  (K=128); exp; accumulate
        float Sr[16], Ar[16];
        #pragma unroll
        for (int q = 0; q < 16; ++q) { Sr[q] = 0.f; Ar[q] = 0.f; }
        #pragma unroll 1
        for (int mt = 0; mt < 2; ++mt) {
            float ra[8][4];
            #pragma unroll
            for (int a = 0; a < 8; ++a)
                { ra[a][0]=0.f; ra[a][1]=0.f; ra[a][2]=0.f; ra[a][3]=0.f; }
            #pragma unroll
            for (int kk = 0; kk < 8; ++kk)
                #pragma unroll
                for (int nt = 0; nt < 8; ++nt) {
                    uint2 b = sWVVf[(kk * 8 + nt) * 32 + lane];
                    mma16(ra[nt], Af[mt][kk], b);
                }
            #pragma unroll
            for (int nt2 = 0; nt2 < 8; ++nt2) {
                float e0 = __expf(sc[mt][nt2][0]);
                float e1 = __expf(sc[mt][nt2][1]);
                float e2 = __expf(sc[mt][nt2][2]);
                float e3 = __expf(sc[mt][nt2][3]);
                Sr[nt2 * 2 + 0] += e0 + e2;
                Sr[nt2 * 2 + 1] += e1 + e3;
                Ar[nt2 * 2 + 0] += e0 * ra[nt2][0] + e2 * ra[nt2][2];
                Ar[nt2 * 2 + 1] += e1 * ra[nt2][1] + e3 * ra[nt2][3];
            }
        }

        // per-tile reduce over g (rows), accumulate into per-warp smem slabs
        #pragma unroll
        for (int q = 0; q < 16; ++q) {
            float s = Sr[q], a = Ar[q];
            s += __shfl_xor_sync(0xffffffffu, s, 4);
            a += __shfl_xor_sync(0xffffffffu, a, 4);
            s += __shfl_xor_sync(0xffffffffu, s, 8);
            a += __shfl_xor_sync(0xffffffffu, a, 8);
            s += __shfl_xor_sync(0xffffffffu, s, 16);
            a += __shfl_xor_sync(0xffffffffu, a, 16);
            Sr[q] = s; Ar[q] = a;
        }
        if (lane < 4) {
            #pragma unroll
            for (int nt2 = 0; nt2 < 8; ++nt2) {
                const int d0 = w * DD + nt2 * 8 + 2 * lane;
                sRedS[d0]     += Sr[nt2 * 2 + 0];
                sRedS[d0 + 1] += Sr[nt2 * 2 + 1];
                sRedA[d0]     += Ar[nt2 * 2 + 0];
                sRedA[d0 + 1] += Ar[nt2 * 2 + 1];
            }
        }
    }

    __syncthreads();
    if (tid < DD) {
        float s = 0.f, a = 0.f;
        #pragma unroll
        for (int q = 0; q < 8; ++q) { s += sRedS[q * DD + tid]; a += sRedA[q * DD + tid]; }
        out[i * DD + tid] = a / s + pb2[tid];
    }
}

// ---------------------------------------------------------------------------
extern "C" void kernel_launch(void* const* d_in, const int* in_sizes, int n_in,
                              void* d_out, int out_size)
{
    const float* x   = (const float*)d_in[0];
    const float* pos = (const float*)d_in[1];
    const float* Wq  = (const float*)d_in[2];
    const float* Wk  = (const float*)d_in[3];
    const float* Wv  = (const float*)d_in[4];
    const float* pW1 = (const float*)d_in[5];
    const float* pb1 = (const float*)d_in[6];
    const float* pW2 = (const float*)d_in[7];
    const float* pb2 = (const float*)d_in[8];
    const float* aW1 = (const float*)d_in[9];
    const float* ab1 = (const float*)d_in[10];
    const float* aW2 = (const float*)d_in[11];
    // d_in[12] = ab2: constant over j -> softmax-invariant -> unused.

    const int N = in_sizes[0] / DD;   // B = 1
    float* out  = (float*)d_out;

    prep1<<<DD, 256>>>(Wq, Wk, pW2, aW1, ab1, pb2);
    prepF<<<56, 256>>>(aW2, pW2, Wv);
    prep2<<<N, 256>>>(x, pos, pW1, N);

    cudaFuncSetAttribute((const void*)pt_main,
                         cudaFuncAttributeMaxDynamicSharedMemorySize, SMEM_SZ);
    pt_main<<<N, 256, SMEM_SZ>>>(pos, pW1, pb1, pb2, out, N);
}

// round 6
// speedup vs baseline: 1.3423x; 1.3423x over previous
#include <cuda_runtime.h>
#include <cuda_fp16.h>
#include <cstdint>

#define DD    64
#define HATTN 256
#define NMAX  2048

// ---------------- device-global scratch (no allocs allowed) ----------------
__device__ float  g_Wqa[DD * HATTN];
__device__ float  g_Wka[DD * HATTN];
__device__ float  g_W12[DD * HATTN];      // (pW2@aW1)[h][c]
__device__ float  g_bqa[HATTN];
__device__ float  g_qa [NMAX * HATTN];    // fp32
__device__ __half g_ax [NMAX * 128];      // per row: [d_j(64) | x_j(64)], d = pos@pW1
// fp16 B-fragment images: uint2 = {half2(k0,k0+1), half2(k0+8,k0+9)} at col n0
__device__ uint2  g_W12f[8192];           // B1 = [W12; -Wka] : [kk=8][nt=32][lane=32]
__device__ uint2  g_aW2f[4096];           // aW2             : [kk=16][nt=8][lane=32]
__device__ uint2  g_Wvvf[2048];           // [pW2; Wv]       : [kk=8][nt=8][lane=32] (stays gmem)

__device__ __forceinline__ unsigned fp2h2(float a, float b) {
    __half2 h = __floats2half2_rn(a, b);
    return *reinterpret_cast<unsigned*>(&h);
}
__device__ __forceinline__ void mma16(float* c, const unsigned* a, uint2 b) {
    asm volatile("mma.sync.aligned.m16n8k16.row.col.f32.f16.f16.f32 "
                 "{%0,%1,%2,%3}, {%4,%5,%6,%7}, {%8,%9}, {%0,%1,%2,%3};"
                 : "+f"(c[0]), "+f"(c[1]), "+f"(c[2]), "+f"(c[3])
                 : "r"(a[0]), "r"(a[1]), "r"(a[2]), "r"(a[3]), "r"(b.x), "r"(b.y));
}

// ---------------------------------------------------------------------------
// prep1: weight folds W12 = pW2@aW1, Wqa = Wq@aW1, Wka = Wk@aW1, bqa.
// ---------------------------------------------------------------------------
__global__ void prep1(const float* __restrict__ Wq, const float* __restrict__ Wk,
                      const float* __restrict__ pW2, const float* __restrict__ aW1,
                      const float* __restrict__ ab1, const float* __restrict__ pb2)
{
    __shared__ float srow[3][DD];
    const int r = blockIdx.x, c = threadIdx.x;
    if (c < 64)       srow[0][c]       = Wq [r * DD + c];
    else if (c < 128) srow[1][c - 64]  = Wk [r * DD + (c - 64)];
    else if (c < 192) srow[2][c - 128] = pW2[r * DD + (c - 128)];
    __syncthreads();
    float wq = 0.f, wk = 0.f, w12 = 0.f;
    #pragma unroll 8
    for (int t = 0; t < DD; ++t) {
        float a = aW1[t * HATTN + c];
        wq  = fmaf(srow[0][t], a, wq);
        wk  = fmaf(srow[1][t], a, wk);
        w12 = fmaf(srow[2][t], a, w12);
    }
    g_Wqa[r * HATTN + c] = wq;
    g_Wka[r * HATTN + c] = wk;
    g_W12[r * HATTN + c] = w12;
    if (r == 0) {
        float b = ab1[c];
        for (int t = 0; t < DD; ++t) b = fmaf(pb2[t], aW1[t * HATTN + c], b);
        g_bqa[c] = b;
    }
}

// ---------------------------------------------------------------------------
// prepF: pack [W12;-Wka] / aW2 / [pW2;Wv] into fp16 B-fragment images.
// ---------------------------------------------------------------------------
__global__ void prepF(const float* __restrict__ aW2, const float* __restrict__ pW2,
                      const float* __restrict__ Wv)
{
    const int e = blockIdx.x * 256 + threadIdx.x;
    const int lane = e & 31, gg = lane >> 2, tg = lane & 3;
    if (e < 8192) {                                      // B1 = [W12; -Wka], K=128, N=256
        const int kk = e >> 10, nt = (e >> 5) & 31;
        const int k0 = 16 * kk + 2 * tg, n0 = 8 * nt + gg;
        auto val = [&](int k) {
            return (k < 64) ? g_W12[k * HATTN + n0] : -g_Wka[(k - 64) * HATTN + n0];
        };
        uint2 v;
        v.x = fp2h2(val(k0),     val(k0 + 1));
        v.y = fp2h2(val(k0 + 8), val(k0 + 9));
        g_W12f[e] = v;
    } else if (e < 12288) {                              // aW2, K=256, N=64
        const int l = e - 8192;
        const int kk = l >> 8, nt = (l >> 5) & 7;
        const int k0 = 16 * kk + 2 * tg, n0 = 8 * nt + gg;
        uint2 v;
        v.x = fp2h2(aW2[(k0    ) * DD + n0], aW2[(k0 + 1) * DD + n0]);
        v.y = fp2h2(aW2[(k0 + 8) * DD + n0], aW2[(k0 + 9) * DD + n0]);
        g_aW2f[l] = v;
    } else if (e < 14336) {                              // [pW2; Wv], K=128, N=64
        const int l = e - 12288;
        const int kk = l >> 8, nt = (l >> 5) & 7;
        const int k0 = 16 * kk + 2 * tg, n0 = 8 * nt + gg;
        auto val = [&](int k) {
            return (k < 64) ? pW2[k * DD + n0] : Wv[(k - 64) * DD + n0];
        };
        uint2 v;
        v.x = fp2h2(val(k0),     val(k0 + 1));
        v.y = fp2h2(val(k0 + 8), val(k0 + 9));
        g_Wvvf[l] = v;
    }
}

// ---------------------------------------------------------------------------
// prep2: qa (fp32) + packed [d|x] row image (fp16). grid N x 256.
// ---------------------------------------------------------------------------
__global__ void prep2(const float* __restrict__ x, const float* __restrict__ pos,
                      const float* __restrict__ pW1, int N)
{
    __shared__ float sx[DD];
    const int n = blockIdx.x, c = threadIdx.x;
    if (c < DD) sx[c] = x[n * DD + c];
    __syncthreads();
    float aq = g_bqa[c];
    #pragma unroll 8
    for (int t = 0; t < DD; ++t) aq = fmaf(sx[t], g_Wqa[t * HATTN + c], aq);
    g_qa[n * HATTN + c] = aq;
    if (c < DD) {
        g_ax[n * 128 + c] = __float2half(fmaf(pos[2 * n], pW1[c],
                                              pos[2 * n + 1] * pW1[DD + c]));
        g_ax[n * 128 + 64 + c] = __float2half(sx[c]);
    }
}

// ---------------------------------------------------------------------------
// main: one CTA per query i; 8 warps x 16 rows = 128-row j-tiles.
// 2 CTAs/SM (regs<=128, smem ~101 KB) for 16 warps of latency hiding.
// ---------------------------------------------------------------------------
#define OFF_W12F 0
#define OFF_AW2F 65536
#define OFF_QA   98304
#define OFF_CI   99328
#define OFF_REDS 99584
#define OFF_REDA 101632
#define SMEM_SZ  103680

__global__ void __launch_bounds__(256, 2)
pt_main(const float* __restrict__ pos, const float* __restrict__ pW1,
        const float* __restrict__ pb1, const float* __restrict__ pb2,
        float* __restrict__ out, int N)
{
    extern __shared__ char smem[];
    uint2* sW12f = (uint2*)(smem + OFF_W12F);
    uint2* sAW2f = (uint2*)(smem + OFF_AW2F);
    float* sQa   = (float*)(smem + OFF_QA);
    float* sCi   = (float*)(smem + OFF_CI);
    float* sRedS = (float*)(smem + OFF_REDS);
    float* sRedA = (float*)(smem + OFF_REDA);

    const int tid  = threadIdx.x;
    const int i    = blockIdx.x;
    const int w    = tid >> 5, lane = tid & 31;
    const int g    = lane >> 2, tig = lane & 3;

    {   // stage W12f / aW2f fragment images (Wvvf stays in gmem: smem budget)
        uint4* d1 = (uint4*)sW12f;  const uint4* s1 = (const uint4*)g_W12f;
        uint4* d2 = (uint4*)sAW2f;  const uint4* s2 = (const uint4*)g_aW2f;
        for (int k = tid; k < 4096; k += 256) d1[k] = s1[k];
        for (int k = tid; k < 2048; k += 256) d2[k] = s2[k];
    }
    sQa[tid] = g_qa[i * HATTN + tid];
    const float posIx = pos[2 * i], posIy = pos[2 * i + 1];
    if (tid < 64)
        sCi[tid] = fmaf(posIx, pW1[tid], fmaf(posIy, pW1[DD + tid], pb1[tid]));
    sRedS[tid] = 0.f; sRedS[tid + 256] = 0.f;
    sRedA[tid] = 0.f; sRedA[tid + 256] = 0.f;
    __syncthreads();

    const int ntile = N >> 7;                 // 128 rows per tile
    for (int jt = 0; jt < ntile; ++jt) {
        const int r0  = (jt << 7) + w * 16;
        const int rlo = r0 + g, rhi = rlo + 8;

        // ---- front-batched A fragments: Af = [U | x] (K=128), 16 rows ----
        unsigned Af[8][4];
        #pragma unroll
        for (int kk = 0; kk < 4; ++kk) {                 // U = relu(ci - d_j)
            const float c0 = sCi[16 * kk + 2 * tig];
            const float c1 = sCi[16 * kk + 2 * tig + 1];
            const float c2 = sCi[16 * kk + 2 * tig + 8];
            const float c3 = sCi[16 * kk + 2 * tig + 9];
            float2 dl0 = __half22float2(*(const __half2*)&g_ax[rlo * 128 + 16 * kk + 2 * tig]);
            float2 dl1 = __half22float2(*(const __half2*)&g_ax[rlo * 128 + 16 * kk + 2 * tig + 8]);
            float2 dh0 = __half22float2(*(const __half2*)&g_ax[rhi * 128 + 16 * kk + 2 * tig]);
            float2 dh1 = __half22float2(*(const __half2*)&g_ax[rhi * 128 + 16 * kk + 2 * tig + 8]);
            Af[kk][0] = fp2h2(fmaxf(c0 - dl0.x, 0.f), fmaxf(c1 - dl0.y, 0.f));
            Af[kk][1] = fp2h2(fmaxf(c0 - dh0.x, 0.f), fmaxf(c1 - dh0.y, 0.f));
            Af[kk][2] = fp2h2(fmaxf(c2 - dl1.x, 0.f), fmaxf(c3 - dl1.y, 0.f));
            Af[kk][3] = fp2h2(fmaxf(c2 - dh1.x, 0.f), fmaxf(c3 - dh1.y, 0.f));
        }
        #pragma unroll
        for (int kk = 0; kk < 4; ++kk) {                 // x passthrough
            Af[4 + kk][0] = *(const unsigned*)&g_ax[rlo * 128 + 64 + 16 * kk + 2 * tig];
            Af[4 + kk][1] = *(const unsigned*)&g_ax[rhi * 128 + 64 + 16 * kk + 2 * tig];
            Af[4 + kk][2] = *(const unsigned*)&g_ax[rlo * 128 + 64 + 16 * kk + 8 + 2 * tig];
            Af[4 + kk][3] = *(const unsigned*)&g_ax[rhi * 128 + 64 + 16 * kk + 8 + 2 * tig];
        }

        float sc[8][4];
        #pragma unroll
        for (int a = 0; a < 8; ++a)
            { sc[a][0]=0.f; sc[a][1]=0.f; sc[a][2]=0.f; sc[a][3]=0.f; }

        #pragma unroll 1
        for (int chk = 0; chk < 8; ++chk) {              // 32 attn channels / chunk
            // GEMM1: P = [U|x] @ [W12;-Wka]  (K=128) -> includes -ka
            float pa[4][4];
            #pragma unroll
            for (int a = 0; a < 4; ++a)
                { pa[a][0]=0.f; pa[a][1]=0.f; pa[a][2]=0.f; pa[a][3]=0.f; }
            #pragma unroll
            for (int kk = 0; kk < 8; ++kk) {
                uint2 b0 = sW12f[((kk * 32) + (chk * 4 + 0)) * 32 + lane];
                uint2 b1 = sW12f[((kk * 32) + (chk * 4 + 1)) * 32 + lane];
                uint2 b2 = sW12f[((kk * 32) + (chk * 4 + 2)) * 32 + lane];
                uint2 b3 = sW12f[((kk * 32) + (chk * 4 + 3)) * 32 + lane];
                mma16(pa[0], Af[kk], b0);
                mma16(pa[1], Af[kk], b1);
                mma16(pa[2], Af[kk], b2);
                mma16(pa[3], Af[kk], b3);
            }
            // epilogue (register-only): + qa, relu, repack as GEMM2 A-frags
            unsigned a2[2][4];
            #pragma unroll
            for (int nt = 0; nt < 4; ++nt) {
                float2 qa2 = *(const float2*)&sQa[chk * 32 + nt * 8 + 2 * tig];
                float v00 = fmaxf(pa[nt][0] + qa2.x, 0.f);
                float v01 = fmaxf(pa[nt][1] + qa2.y, 0.f);
                float v10 = fmaxf(pa[nt][2] + qa2.x, 0.f);
                float v11 = fmaxf(pa[nt][3] + qa2.y, 0.f);
                const int kk2 = nt >> 1, sl = (nt & 1) << 1;
                a2[kk2][sl]     = fp2h2(v00, v01);
                a2[kk2][sl + 1] = fp2h2(v10, v11);
            }
            // GEMM2 partial: sim += P' @ aW2  (K=32 this chunk)
            #pragma unroll
            for (int kk2 = 0; kk2 < 2; ++kk2)
                #pragma unroll
                for (int nt2 = 0; nt2 < 8; ++nt2) {
                    uint2 b = sAW2f[(((chk * 2 + kk2) * 8) + nt2) * 32 + lane];
                    mma16(sc[nt2], a2[kk2], b);
                }
        }

        // GEMM3: vv' = [U|x] @ [pW2;Wv]  (K=128), B-frags streamed from gmem (L1/L2-hot)
        float ra[8][4];
        #pragma unroll
        for (int a = 0; a < 8; ++a)
            { ra[a][0]=0.f; ra[a][1]=0.f; ra[a][2]=0.f; ra[a][3]=0.f; }
        #pragma unroll
        for (int kk = 0; kk < 8; ++kk)
            #pragma unroll
            for (int nt = 0; nt < 8; ++nt) {
                uint2 b = __ldg(&g_Wvvf[(kk * 8 + nt) * 32 + lane]);
                mma16(ra[nt], Af[kk], b);
            }

        // exp + weighted accumulation, then per-tile reduce over rows
        float Sr[16], Ar[16];
        #pragma unroll
        for (int nt2 = 0; nt2 < 8; ++nt2) {
            float e0 = __expf(sc[nt2][0]);
            float e1 = __expf(sc[nt2][1]);
            float e2 = __expf(sc[nt2][2]);
            float e3 = __expf(sc[nt2][3]);
            Sr[nt2 * 2 + 0] = e0 + e2;
            Sr[nt2 * 2 + 1] = e1 + e3;
            Ar[nt2 * 2 + 0] = e0 * ra[nt2][0] + e2 * ra[nt2][2];
            Ar[nt2 * 2 + 1] = e1 * ra[nt2][1] + e3 * ra[nt2][3];
        }
        #pragma unroll
        for (int q = 0; q < 16; ++q) {
            float s = Sr[q], a = Ar[q];
            s += __shfl_xor_sync(0xffffffffu, s, 4);
            a += __shfl_xor_sync(0xffffffffu, a, 4);
            s += __shfl_xor_sync(0xffffffffu, s, 8);
            a += __shfl_xor_sync(0xffffffffu, a, 8);
            s += __shfl_xor_sync(0xffffffffu, s, 16);
            a += __shfl_xor_sync(0xffffffffu, a, 16);
            Sr[q] = s; Ar[q] = a;
        }
        if (lane < 4) {
            #pragma unroll
            for (int nt2 = 0; nt2 < 8; ++nt2) {
                const int d0 = w * DD + nt2 * 8 + 2 * lane;
                sRedS[d0]     += Sr[nt2 * 2 + 0];
                sRedS[d0 + 1] += Sr[nt2 * 2 + 1];
                sRedA[d0]     += Ar[nt2 * 2 + 0];
                sRedA[d0 + 1] += Ar[nt2 * 2 + 1];
            }
        }
    }

    __syncthreads();
    if (tid < DD) {
        float s = 0.f, a = 0.f;
        #pragma unroll
        for (int q = 0; q < 8; ++q) { s += sRedS[q * DD + tid]; a += sRedA[q * DD + tid]; }
        out[i * DD + tid] = a / s + pb2[tid];
    }
}

// ---------------------------------------------------------------------------
extern "C" void kernel_launch(void* const* d_in, const int* in_sizes, int n_in,
                              void* d_out, int out_size)
{
    const float* x   = (const float*)d_in[0];
    const float* pos = (const float*)d_in[1];
    const float* Wq  = (const float*)d_in[2];
    const float* Wk  = (const float*)d_in[3];
    const float* Wv  = (const float*)d_in[4];
    const float* pW1 = (const float*)d_in[5];
    const float* pb1 = (const float*)d_in[6];
    const float* pW2 = (const float*)d_in[7];
    const float* pb2 = (const float*)d_in[8];
    const float* aW1 = (const float*)d_in[9];
    const float* ab1 = (const float*)d_in[10];
    const float* aW2 = (const float*)d_in[11];
    // d_in[12] = ab2: constant over j -> softmax-invariant -> unused.

    const int N = in_sizes[0] / DD;   // B = 1
    float* out  = (float*)d_out;

    prep1<<<DD, 256>>>(Wq, Wk, pW2, aW1, ab1, pb2);
    prepF<<<56, 256>>>(aW2, pW2, Wv);
    prep2<<<N, 256>>>(x, pos, pW1, N);

    cudaFuncSetAttribute((const void*)pt_main,
                         cudaFuncAttributeMaxDynamicSharedMemorySize, SMEM_SZ);
    pt_main<<<N, 256, SMEM_SZ>>>(pos, pW1, pb1, pb2, out, N);
}

// round 7
// speedup vs baseline: 1.7893x; 1.3330x over previous
#include <cuda_runtime.h>
#include <cuda_fp16.h>
#include <cstdint>

#define DD    64
#define HATTN 256
#define NMAX  2048

// ---------------- device-global scratch (no allocs allowed) ----------------
__device__ float  g_Wqa[DD * HATTN];
__device__ float  g_Wka[DD * HATTN];
__device__ float  g_W12[DD * HATTN];      // (pW2@aW1)[h][c]
__device__ float  g_bqa[HATTN];
__device__ float  g_qa [NMAX * HATTN];    // fp32
__device__ __half g_d16[NMAX * DD];       // d_j = pos_j @ pW1 (no bias)
// fragment-ordered fp16 data images (one coalesced LDG.64 per fragment):
__device__ uint2  g_kaf[(NMAX / 16) * 8 * 4 * 32];  // ka: [rb][chk][nt][lane]
__device__ uint2  g_vsf[(NMAX / 16) * 8 * 32];      // vs=x@Wv: [rb][nt2][lane]
// fp16 B-fragment weight images: uint2 = {half2(k0,k0+1), half2(k0+8,k0+9)} at col n0
__device__ uint2  g_W1f [4096];           // W12 : K=64 [kk=4][ntg=32][lane=32]
__device__ uint2  g_aW2f[4096];           // aW2 : K=256 [kk=16][nt=8][lane=32]
__device__ uint2  g_pW2f[1024];           // pW2 : K=64 [kk=4][nt=8][lane=32]

__device__ __forceinline__ unsigned fp2h2(float a, float b) {
    __half2 h = __floats2half2_rn(a, b);
    return *reinterpret_cast<unsigned*>(&h);
}
__device__ __forceinline__ void mma16(float* c, const unsigned* a, uint2 b) {
    asm volatile("mma.sync.aligned.m16n8k16.row.col.f32.f16.f16.f32 "
                 "{%0,%1,%2,%3}, {%4,%5,%6,%7}, {%8,%9}, {%0,%1,%2,%3};"
                 : "+f"(c[0]), "+f"(c[1]), "+f"(c[2]), "+f"(c[3])
                 : "r"(a[0]), "r"(a[1]), "r"(a[2]), "r"(a[3]), "r"(b.x), "r"(b.y));
}

// ---------------------------------------------------------------------------
// prep1: weight folds W12 = pW2@aW1, Wqa = Wq@aW1, Wka = Wk@aW1, bqa.
// ---------------------------------------------------------------------------
__global__ void prep1(const float* __restrict__ Wq, const float* __restrict__ Wk,
                      const float* __restrict__ pW2, const float* __restrict__ aW1,
                      const float* __restrict__ ab1, const float* __restrict__ pb2)
{
    __shared__ float srow[3][DD];
    const int r = blockIdx.x, c = threadIdx.x;
    if (c < 64)       srow[0][c]       = Wq [r * DD + c];
    else if (c < 128) srow[1][c - 64]  = Wk [r * DD + (c - 64)];
    else if (c < 192) srow[2][c - 128] = pW2[r * DD + (c - 128)];
    __syncthreads();
    float wq = 0.f, wk = 0.f, w12 = 0.f;
    #pragma unroll 8
    for (int t = 0; t < DD; ++t) {
        float a = aW1[t * HATTN + c];
        wq  = fmaf(srow[0][t], a, wq);
        wk  = fmaf(srow[1][t], a, wk);
        w12 = fmaf(srow[2][t], a, w12);
    }
    g_Wqa[r * HATTN + c] = wq;
    g_Wka[r * HATTN + c] = wk;
    g_W12[r * HATTN + c] = w12;
    if (r == 0) {
        float b = ab1[c];
        for (int t = 0; t < DD; ++t) b = fmaf(pb2[t], aW1[t * HATTN + c], b);
        g_bqa[c] = b;
    }
}

// ---------------------------------------------------------------------------
// prepF: pack W12 / aW2 / pW2 into fp16 B-fragment images (9216 entries).
// ---------------------------------------------------------------------------
__global__ void prepF(const float* __restrict__ aW2, const float* __restrict__ pW2)
{
    const int e = blockIdx.x * 256 + threadIdx.x;
    const int lane = e & 31, gg = lane >> 2, tg = lane & 3;
    if (e < 4096) {                                      // W12, K=64, N=256
        const int kk = e >> 10, nt = (e >> 5) & 31;
        const int k0 = 16 * kk + 2 * tg, n0 = 8 * nt + gg;
        uint2 v;
        v.x = fp2h2(g_W12[(k0    ) * HATTN + n0], g_W12[(k0 + 1) * HATTN + n0]);
        v.y = fp2h2(g_W12[(k0 + 8) * HATTN + n0], g_W12[(k0 + 9) * HATTN + n0]);
        g_W1f[e] = v;
    } else if (e < 8192) {                               // aW2, K=256, N=64
        const int l = e - 4096;
        const int kk = l >> 8, nt = (l >> 5) & 7;
        const int k0 = 16 * kk + 2 * tg, n0 = 8 * nt + gg;
        uint2 v;
        v.x = fp2h2(aW2[(k0    ) * DD + n0], aW2[(k0 + 1) * DD + n0]);
        v.y = fp2h2(aW2[(k0 + 8) * DD + n0], aW2[(k0 + 9) * DD + n0]);
        g_aW2f[l] = v;
    } else if (e < 9216) {                               // pW2, K=64, N=64
        const int l = e - 8192;
        const int kk = l >> 8, nt = (l >> 5) & 7;
        const int k0 = 16 * kk + 2 * tg, n0 = 8 * nt + gg;
        uint2 v;
        v.x = fp2h2(pW2[(k0    ) * DD + n0], pW2[(k0 + 1) * DD + n0]);
        v.y = fp2h2(pW2[(k0 + 8) * DD + n0], pW2[(k0 + 9) * DD + n0]);
        g_pW2f[l] = v;
    }
}

// ---------------------------------------------------------------------------
// prep2: qa (fp32), d (fp16), ka/vs in fragment-ordered fp16. grid N x 256.
// ---------------------------------------------------------------------------
__global__ void prep2(const float* __restrict__ x, const float* __restrict__ pos,
                      const float* __restrict__ Wv, const float* __restrict__ pW1,
                      int N)
{
    __shared__ float sx[DD];
    const int n = blockIdx.x, c = threadIdx.x;
    if (c < DD) sx[c] = x[n * DD + c];
    __syncthreads();
    float aq = g_bqa[c], ak = 0.f;
    #pragma unroll 8
    for (int t = 0; t < DD; ++t) {
        float xv = sx[t];
        aq = fmaf(xv, g_Wqa[t * HATTN + c], aq);
        ak = fmaf(xv, g_Wka[t * HATTN + c], ak);
    }
    g_qa[n * HATTN + c] = aq;
    // ka -> fragment image: entry [rb][chk][nt][lane], halves {g:c0,c0+1 | g+8:c0,c0+1}
    const int rb = n >> 4, rr = n & 15, gg = rr & 7, hi = rr >> 3;
    {
        const int chk = c >> 5, nt = (c >> 3) & 3, tg = (c & 7) >> 1, lo = c & 1;
        const int ent = ((rb * 8 + chk) * 4 + nt) * 32 + (gg * 4 + tg);
        reinterpret_cast<__half*>(g_kaf)[ent * 4 + hi * 2 + lo] = __float2half(ak);
    }
    if (c < DD) {
        float av = 0.f;
        for (int t = 0; t < DD; ++t) av = fmaf(sx[t], Wv[t * DD + c], av);
        const int nt2 = c >> 3, tg = (c & 7) >> 1, lo = c & 1;
        const int ent = (rb * 8 + nt2) * 32 + (gg * 4 + tg);
        reinterpret_cast<__half*>(g_vsf)[ent * 4 + hi * 2 + lo] = __float2half(av);
        g_d16[n * DD + c] = __float2half(fmaf(pos[2 * n], pW1[c],
                                              pos[2 * n + 1] * pW1[DD + c]));
    }
}

// ---------------------------------------------------------------------------
// main: one CTA per query i; 8 warps x 16 rows = 128-row j-tiles; 2 CTAs/SM.
// GEMMs at K=64 on U only; ka/vs enter via coalesced fragment LDG.
// ---------------------------------------------------------------------------
#define OFF_W1F  0
#define OFF_AW2F 32768
#define OFF_PW2F 65536
#define OFF_QA   73728
#define OFF_CI   74752
#define OFF_REDS 75008
#define OFF_REDA 77056
#define SMEM_SZ  79104

__global__ void __launch_bounds__(256, 2)
pt_main(const float* __restrict__ pos, const float* __restrict__ pW1,
        const float* __restrict__ pb1, const float* __restrict__ pb2,
        float* __restrict__ out, int N)
{
    extern __shared__ char smem[];
    uint2* sW1f  = (uint2*)(smem + OFF_W1F);
    uint2* sAW2f = (uint2*)(smem + OFF_AW2F);
    uint2* sPW2f = (uint2*)(smem + OFF_PW2F);
    float* sQa   = (float*)(smem + OFF_QA);
    float* sCi   = (float*)(smem + OFF_CI);
    float* sRedS = (float*)(smem + OFF_REDS);
    float* sRedA = (float*)(smem + OFF_REDA);

    const int tid  = threadIdx.x;
    const int i    = blockIdx.x;
    const int w    = tid >> 5, lane = tid & 31;
    const int g    = lane >> 2, tig = lane & 3;

    {   // stage weight fragment images
        uint4* d1 = (uint4*)sW1f;   const uint4* s1 = (const uint4*)g_W1f;
        uint4* d2 = (uint4*)sAW2f;  const uint4* s2 = (const uint4*)g_aW2f;
        uint4* d3 = (uint4*)sPW2f;  const uint4* s3 = (const uint4*)g_pW2f;
        for (int k = tid; k < 2048; k += 256) { d1[k] = s1[k]; d2[k] = s2[k]; }
        for (int k = tid; k < 512;  k += 256) d3[k] = s3[k];
    }
    sQa[tid] = g_qa[i * HATTN + tid];
    const float posIx = pos[2 * i], posIy = pos[2 * i + 1];
    if (tid < 64)
        sCi[tid] = fmaf(posIx, pW1[tid], fmaf(posIy, pW1[DD + tid], pb1[tid]));
    sRedS[tid] = 0.f; sRedS[tid + 256] = 0.f;
    sRedA[tid] = 0.f; sRedA[tid + 256] = 0.f;
    __syncthreads();

    const int ntile = N >> 7;                 // 128 rows per tile
    for (int jt = 0; jt < ntile; ++jt) {
        const int rb  = jt * 8 + w;           // this warp's 16-row block
        const int rlo = rb * 16 + g, rhi = rlo + 8;
        const uint2* kaRow = &g_kaf[rb * 8 * 4 * 32];
        const uint2* vsRow = &g_vsf[rb * 8 * 32];

        // ---- A fragments: U = relu(ci - d_j), K=64 ----
        unsigned Af[4][4];
        #pragma unroll
        for (int kk = 0; kk < 4; ++kk) {
            const float c0 = sCi[16 * kk + 2 * tig];
            const float c1 = sCi[16 * kk + 2 * tig + 1];
            const float c2 = sCi[16 * kk + 2 * tig + 8];
            const float c3 = sCi[16 * kk + 2 * tig + 9];
            float2 dl0 = __half22float2(*(const __half2*)&g_d16[rlo * DD + 16 * kk + 2 * tig]);
            float2 dl1 = __half22float2(*(const __half2*)&g_d16[rlo * DD + 16 * kk + 2 * tig + 8]);
            float2 dh0 = __half22float2(*(const __half2*)&g_d16[rhi * DD + 16 * kk + 2 * tig]);
            float2 dh1 = __half22float2(*(const __half2*)&g_d16[rhi * DD + 16 * kk + 2 * tig + 8]);
            Af[kk][0] = fp2h2(fmaxf(c0 - dl0.x, 0.f), fmaxf(c1 - dl0.y, 0.f));
            Af[kk][1] = fp2h2(fmaxf(c0 - dh0.x, 0.f), fmaxf(c1 - dh0.y, 0.f));
            Af[kk][2] = fp2h2(fmaxf(c2 - dl1.x, 0.f), fmaxf(c3 - dl1.y, 0.f));
            Af[kk][3] = fp2h2(fmaxf(c2 - dh1.x, 0.f), fmaxf(c3 - dh1.y, 0.f));
        }

        float sc[8][4];
        #pragma unroll
        for (int a = 0; a < 8; ++a)
            { sc[a][0]=0.f; sc[a][1]=0.f; sc[a][2]=0.f; sc[a][3]=0.f; }

        #pragma unroll 1
        for (int chk = 0; chk < 8; ++chk) {              // 32 attn channels / chunk
            // ka fragments for this chunk (coalesced LDG.64; overlaps GEMM1)
            uint2 kafr[4];
            #pragma unroll
            for (int nt = 0; nt < 4; ++nt)
                kafr[nt] = __ldg(&kaRow[(chk * 4 + nt) * 32 + lane]);

            // GEMM1: P = U @ W12 (K=64)
            float pa[4][4];
            #pragma unroll
            for (int a = 0; a < 4; ++a)
                { pa[a][0]=0.f; pa[a][1]=0.f; pa[a][2]=0.f; pa[a][3]=0.f; }
            #pragma unroll
            for (int kk = 0; kk < 4; ++kk) {
                uint2 b0 = sW1f[((kk * 32) + (chk * 4 + 0)) * 32 + lane];
                uint2 b1 = sW1f[((kk * 32) + (chk * 4 + 1)) * 32 + lane];
                uint2 b2 = sW1f[((kk * 32) + (chk * 4 + 2)) * 32 + lane];
                uint2 b3 = sW1f[((kk * 32) + (chk * 4 + 3)) * 32 + lane];
                mma16(pa[0], Af[kk], b0);
                mma16(pa[1], Af[kk], b1);
                mma16(pa[2], Af[kk], b2);
                mma16(pa[3], Af[kk], b3);
            }
            // epilogue: + qa - ka, relu, repack as GEMM2 A-frags (registers only)
            unsigned a2[2][4];
            #pragma unroll
            for (int nt = 0; nt < 4; ++nt) {
                float2 qa2 = *(const float2*)&sQa[chk * 32 + nt * 8 + 2 * tig];
                float2 kl = __half22float2(*(const __half2*)&kafr[nt].x);
                float2 kh = __half22float2(*(const __half2*)&kafr[nt].y);
                float v00 = fmaxf(pa[nt][0] + qa2.x - kl.x, 0.f);
                float v01 = fmaxf(pa[nt][1] + qa2.y - kl.y, 0.f);
                float v10 = fmaxf(pa[nt][2] + qa2.x - kh.x, 0.f);
                float v11 = fmaxf(pa[nt][3] + qa2.y - kh.y, 0.f);
                const int kk2 = nt >> 1, sl = (nt & 1) << 1;
                a2[kk2][sl]     = fp2h2(v00, v01);
                a2[kk2][sl + 1] = fp2h2(v10, v11);
            }
            // GEMM2 partial: sim += P' @ aW2  (K=32 this chunk)
            #pragma unroll
            for (int kk2 = 0; kk2 < 2; ++kk2)
                #pragma unroll
                for (int nt2 = 0; nt2 < 8; ++nt2) {
                    uint2 b = sAW2f[(((chk * 2 + kk2) * 8) + nt2) * 32 + lane];
                    mma16(sc[nt2], a2[kk2], b);
                }
        }

        // vs fragments (coalesced LDG.64; overlap GEMM3)
        uint2 vsfr[8];
        #pragma unroll
        for (int nt2 = 0; nt2 < 8; ++nt2)
            vsfr[nt2] = __ldg(&vsRow[nt2 * 32 + lane]);

        // GEMM3: rpe = U @ pW2 (K=64)
        float ra[8][4];
        #pragma unroll
        for (int a = 0; a < 8; ++a)
            { ra[a][0]=0.f; ra[a][1]=0.f; ra[a][2]=0.f; ra[a][3]=0.f; }
        #pragma unroll
        for (int kk = 0; kk < 4; ++kk)
            #pragma unroll
            for (int nt = 0; nt < 8; ++nt) {
                uint2 b = sPW2f[(kk * 8 + nt) * 32 + lane];
                mma16(ra[nt], Af[kk], b);
            }

        // exp + weighted accumulation, then per-tile reduce over rows
        float Sr[16], Ar[16];
        #pragma unroll
        for (int nt2 = 0; nt2 < 8; ++nt2) {
            float2 vl = __half22float2(*(const __half2*)&vsfr[nt2].x);
            float2 vh = __half22float2(*(const __half2*)&vsfr[nt2].y);
            float e0 = __expf(sc[nt2][0]);
            float e1 = __expf(sc[nt2][1]);
            float e2 = __expf(sc[nt2][2]);
            float e3 = __expf(sc[nt2][3]);
            Sr[nt2 * 2 + 0] = e0 + e2;
            Sr[nt2 * 2 + 1] = e1 + e3;
            Ar[nt2 * 2 + 0] = e0 * (vl.x + ra[nt2][0]) + e2 * (vh.x + ra[nt2][2]);
            Ar[nt2 * 2 + 1] = e1 * (vl.y + ra[nt2][1]) + e3 * (vh.y + ra[nt2][3]);
        }
        #pragma unroll
        for (int q = 0; q < 16; ++q) {
            float s = Sr[q], a = Ar[q];
            s += __shfl_xor_sync(0xffffffffu, s, 4);
            a += __shfl_xor_sync(0xffffffffu, a, 4);
            s += __shfl_xor_sync(0xffffffffu, s, 8);
            a += __shfl_xor_sync(0xffffffffu, a, 8);
            s += __shfl_xor_sync(0xffffffffu, s, 16);
            a += __shfl_xor_sync(0xffffffffu, a, 16);
            Sr[q] = s; Ar[q] = a;
        }
        if (lane < 4) {
            #pragma unroll
            for (int nt2 = 0; nt2 < 8; ++nt2) {
                const int d0 = w * DD + nt2 * 8 + 2 * lane;
                sRedS[d0]     += Sr[nt2 * 2 + 0];
                sRedS[d0 + 1] += Sr[nt2 * 2 + 1];
                sRedA[d0]     += Ar[nt2 * 2 + 0];
                sRedA[d0 + 1] += Ar[nt2 * 2 + 1];
            }
        }
    }

    __syncthreads();
    if (tid < DD) {
        float s = 0.f, a = 0.f;
        #pragma unroll
        for (int q = 0; q < 8; ++q) { s += sRedS[q * DD + tid]; a += sRedA[q * DD + tid]; }
        out[i * DD + tid] = a / s + pb2[tid];
    }
}

// ---------------------------------------------------------------------------
extern "C" void kernel_launch(void* const* d_in, const int* in_sizes, int n_in,
                              void* d_out, int out_size)
{
    const float* x   = (const float*)d_in[0];
    const float* pos = (const float*)d_in[1];
    const float* Wq  = (const float*)d_in[2];
    const float* Wk  = (const float*)d_in[3];
    const float* Wv  = (const float*)d_in[4];
    const float* pW1 = (const float*)d_in[5];
    const float* pb1 = (const float*)d_in[6];
    const float* pW2 = (const float*)d_in[7];
    const float* pb2 = (const float*)d_in[8];
    const float* aW1 = (const float*)d_in[9];
    const float* ab1 = (const float*)d_in[10];
    const float* aW2 = (const float*)d_in[11];
    // d_in[12] = ab2: constant over j -> softmax-invariant -> unused.

    const int N = in_sizes[0] / DD;   // B = 1
    float* out  = (float*)d_out;

    prep1<<<DD, 256>>>(Wq, Wk, pW2, aW1, ab1, pb2);
    prepF<<<36, 256>>>(aW2, pW2);
    prep2<<<N, 256>>>(x, pos, Wv, pW1, N);

    cudaFuncSetAttribute((const void*)pt_main,
                         cudaFuncAttributeMaxDynamicSharedMemorySize, SMEM_SZ);
    pt_main<<<N, 256, SMEM_SZ>>>(pos, pW1, pb1, pb2, out, N);
}